// round 16
// baseline (speedup 1.0000x reference)
#include <cuda_runtime.h>
#include <cuda_fp16.h>
#include <cuda_bf16.h>
#include <math.h>
#include <stdint.h>

#define BATCH   4
#define SEQ     4096
#define HID     2048
#define HEADD   256
#define VDIM    512
#define MROWS   (BATCH*SEQ)

#define LOG2_GAMMA (-0.045803686185410744f)
#define GAMMA_INV  (1.0322580645161290f)
#define GAMMA_P8   (0.7756998776f)
#define GAMMA_M8   (1.2891590567f)
#define WINDOW     7
#define L2_1E4_128 (0.10380962796523007f)

// Scratch (__device__ globals: allocation-free rule)
__device__ __half         g_Xh[(size_t)MROWS * HID];     // X fp16
__device__ __half         g_Wh[(size_t)HID * 1024];      // [WQ|WK|WV]*1024 fp16
__device__ __nv_bfloat16  g_Qh[(size_t)MROWS * HEADD];   // Q̃*64 bf16 hi
__device__ __nv_bfloat16  g_Ql[(size_t)MROWS * HEADD];   // Q̃*64 bf16 lo
__device__ __nv_bfloat16  g_Kh[(size_t)MROWS * HEADD];   // K̃*64 bf16 hi
__device__ __nv_bfloat16  g_Kl[(size_t)MROWS * HEADD];   // K̃*64 bf16 lo
__device__ __half         g_Vh[(size_t)MROWS * VDIM];    // V*64 fp16

// ---------------------------------------------------------------------------
__device__ __forceinline__ uint32_t smem_u32(const void* p) {
    uint32_t a;
    asm("{ .reg .u64 t; cvta.to.shared.u64 t, %1; cvt.u32.u64 %0, t; }" : "=r"(a) : "l"(p));
    return a;
}
__device__ __forceinline__ void cp_async16(uint32_t s, const void* g) {
    asm volatile("cp.async.cg.shared.global [%0], [%1], 16;" :: "r"(s), "l"(g) : "memory");
}
#define CP_COMMIT()  asm volatile("cp.async.commit_group;" ::: "memory")
#define CP_WAIT(N)   asm volatile("cp.async.wait_group %0;" :: "n"(N) : "memory")

__device__ __forceinline__ void ldm_x4(uint32_t* r, uint32_t a) {
    asm volatile("ldmatrix.sync.aligned.m8n8.x4.shared.b16 {%0,%1,%2,%3}, [%4];"
                 : "=r"(r[0]), "=r"(r[1]), "=r"(r[2]), "=r"(r[3]) : "r"(a));
}
__device__ __forceinline__ void ldm_x4t(uint32_t* r, uint32_t a) {
    asm volatile("ldmatrix.sync.aligned.m8n8.x4.trans.shared.b16 {%0,%1,%2,%3}, [%4];"
                 : "=r"(r[0]), "=r"(r[1]), "=r"(r[2]), "=r"(r[3]) : "r"(a));
}
__device__ __forceinline__ void ldm_x2(uint32_t* r, uint32_t a) {
    asm volatile("ldmatrix.sync.aligned.m8n8.x2.shared.b16 {%0,%1}, [%2];"
                 : "=r"(r[0]), "=r"(r[1]) : "r"(a));
}
__device__ __forceinline__ void mma16(float* d, const uint32_t* a, const uint32_t* b) {
    asm volatile("mma.sync.aligned.m16n8k16.row.col.f32.f16.f16.f32 "
                 "{%0,%1,%2,%3},{%4,%5,%6,%7},{%8,%9},{%0,%1,%2,%3};"
                 : "+f"(d[0]), "+f"(d[1]), "+f"(d[2]), "+f"(d[3])
                 : "r"(a[0]), "r"(a[1]), "r"(a[2]), "r"(a[3]), "r"(b[0]), "r"(b[1]));
}
__device__ __forceinline__ void mma16b(float* d, const uint32_t* a, const uint32_t* b) {
    asm volatile("mma.sync.aligned.m16n8k16.row.col.f32.bf16.bf16.f32 "
                 "{%0,%1,%2,%3},{%4,%5,%6,%7},{%8,%9},{%0,%1,%2,%3};"
                 : "+f"(d[0]), "+f"(d[1]), "+f"(d[2]), "+f"(d[3])
                 : "r"(a[0]), "r"(a[1]), "r"(a[2]), "r"(a[3]), "r"(b[0]), "r"(b[1]));
}
__device__ __forceinline__ void hsplit(float x, __half& hi, __half& lo) {
    hi = __float2half_rn(x);
    lo = __float2half_rn(x - __half2float(hi));
}
__device__ __forceinline__ void bsplit(float x, __nv_bfloat16& hi, __nv_bfloat16& lo) {
    hi = __float2bfloat16_rn(x);
    lo = __float2bfloat16_rn(x - __bfloat162float(hi));
}

// ===========================================================================
// Pre-convert kernels (unchanged)
// ===========================================================================
__global__ void __launch_bounds__(256) convert_x_kernel(const float* __restrict__ X)
{
    const size_t base = ((size_t)blockIdx.x * 256 + threadIdx.x) * 8;
    float4 a = *(const float4*)(X + base);
    float4 b = *(const float4*)(X + base + 4);
    __half2 ph[4];
    ph[0] = __halves2half2(__float2half_rn(a.x), __float2half_rn(a.y));
    ph[1] = __halves2half2(__float2half_rn(a.z), __float2half_rn(a.w));
    ph[2] = __halves2half2(__float2half_rn(b.x), __float2half_rn(b.y));
    ph[3] = __halves2half2(__float2half_rn(b.z), __float2half_rn(b.w));
    *(uint4*)(g_Xh + base) = *(uint4*)ph;
}

__global__ void __launch_bounds__(256) convert_w_kernel(const float* __restrict__ WQ,
                                                        const float* __restrict__ WK,
                                                        const float* __restrict__ WV)
{
    const int idx = blockIdx.x * 256 + threadIdx.x;
    const int k = idx >> 10, n = idx & 1023;
    float v;
    if (n < 256)      v = WQ[k * 256 + n];
    else if (n < 512) v = WK[k * 256 + (n - 256)];
    else              v = WV[k * 512 + (n - 512)];
    g_Wh[idx] = __float2half_rn(v * 1024.0f);
}

// ===========================================================================
// Projection (R15 mainloop; epilogue writes bf16 hi/lo planes, scale x64)
// ===========================================================================
#define PA 40
#define PB 136
#define APL(s)    ((s) * 128 * PA)
#define BPL(s)    (3 * 128 * PA + (s) * 32 * PB)
#define PROJ_SMEM ((3 * 128 * PA + 3 * 32 * PB) * 2)

__device__ __forceinline__ void proj_issue(uint32_t sb, int s, int chunk,
                                           int m0, int nbase, int tid)
{
    const int k0 = chunk * 32;
#pragma unroll
    for (int i = 0; i < 2; i++) {
        const int idx = tid + i * 256;
        const int row = idx >> 2;
        const int j = idx & 3;
        cp_async16(sb + (uint32_t)(APL(s) + row * PA + j * 8) * 2,
                   g_Xh + (size_t)(m0 + row) * HID + k0 + j * 8);
    }
#pragma unroll
    for (int i = 0; i < 2; i++) {
        const int idx = tid + i * 256;
        const int row = idx >> 4;
        const int j = idx & 15;
        cp_async16(sb + (uint32_t)(BPL(s) + row * PB + j * 8) * 2,
                   g_Wh + (size_t)(k0 + row) * 1024 + nbase + j * 8);
    }
    CP_COMMIT();
}

__global__ void __launch_bounds__(256, 2) proj_kernel()
{
    extern __shared__ __align__(16) __half sm[];
    const uint32_t sb = smem_u32(sm);

    const int tid = threadIdx.x, wid = tid >> 5, lane = tid & 31;
    const int g = lane >> 2, tg = lane & 3;
    const int m0 = blockIdx.y * 128;
    const int job = blockIdx.x;
    const int nbase = job * 128;

    const int wm = (wid >> 2) * 64, wn = (wid & 3) * 32;
    const int arow_f = lane & 15;
    const int acol_f = (lane >> 4) << 3;
    const int b4row_f = lane & 15;
    const int b4col_f = (lane >> 4) << 3;

    float acc[4][4][4];
#pragma unroll
    for (int a = 0; a < 4; a++)
#pragma unroll
        for (int b = 0; b < 4; b++)
#pragma unroll
            for (int c = 0; c < 4; c++) acc[a][b][c] = 0.0f;

    proj_issue(sb, 0, 0, m0, nbase, tid);
    proj_issue(sb, 1, 1, m0, nbase, tid);

    for (int kb = 0; kb < 64; kb++) {
        const int s = kb % 3;
        if (kb < 63) { CP_WAIT(1); } else { CP_WAIT(0); }
        __syncthreads();
        if (kb + 2 < 64) proj_issue(sb, (kb + 2) % 3, kb + 2, m0, nbase, tid);

#pragma unroll
        for (int k2 = 0; k2 < 2; k2++) {
            const int kk = k2 * 16;
            uint32_t ah[4][4], bh[4][2];
#pragma unroll
            for (int mf = 0; mf < 4; mf++) {
                const uint32_t off = (uint32_t)((wm + mf * 16 + arow_f) * PA + kk + acol_f) * 2;
                ldm_x4(ah[mf], sb + (uint32_t)APL(s) * 2 + off);
            }
#pragma unroll
            for (int p = 0; p < 2; p++) {
                const uint32_t off = (uint32_t)((kk + b4row_f) * PB + wn + p * 16 + b4col_f) * 2;
                ldm_x4t(&bh[p * 2][0], sb + (uint32_t)BPL(s) * 2 + off);
            }
#pragma unroll
            for (int mf = 0; mf < 4; mf++)
#pragma unroll
                for (int nf = 0; nf < 4; nf++)
                    mma16(acc[mf][nf], ah[mf], bh[nf]);
        }
    }

    const int mode = (job < 2) ? 1 : (job < 4) ? 2 : 0;

    if (mode != 0) {
        float invf_v[4], lgsv_v[4];
#pragma unroll
        for (int nf = 0; nf < 4; nf++) {
            const int nn = (nbase + wn + nf * 8 + 2 * tg) & 255;
            invf_v[nf] = exp2f((float)(nn >> 1) * (-L2_1E4_128));
            lgsv_v[nf] = __log2f(((float)nn + 102.4f) * (1.0f / 358.4f));
        }
        __nv_bfloat16* dh = (mode == 1) ? g_Qh : g_Kh;
        __nv_bfloat16* dl = (mode == 1) ? g_Ql : g_Kl;
        const float sgn = (mode == 1) ? (1.0f / 512.0f) : (-1.0f / 512.0f);
#pragma unroll
        for (int mf = 0; mf < 4; mf++) {
#pragma unroll
            for (int half = 0; half < 2; half++) {
                const int m = m0 + wm + mf * 16 + g + half * 8;
                const float spos = (float)(m & (SEQ - 1));
                const float e512 = spos * sgn;
#pragma unroll
                for (int nf = 0; nf < 4; nf++) {
                    const int nn = (nbase + wn + nf * 8 + 2 * tg) & 255;
                    float e = acc[mf][nf][half * 2]     * (1.0f / 1024.0f);
                    float o = acc[mf][nf][half * 2 + 1] * (1.0f / 1024.0f);
                    float sn, cs;
                    sincosf(spos * invf_v[nf], &sn, &cs);
                    const float sc = exp2f(lgsv_v[nf] * e512 + 6.0f);   // x64
                    const float ne = (e * cs - o * sn) * sc;
                    const float no = (o * cs + e * sn) * sc;
                    __nv_bfloat16 h0, l0, h1, l1;
                    bsplit(ne, h0, l0);
                    bsplit(no, h1, l1);
                    *(__nv_bfloat162*)&dh[(size_t)m * HEADD + nn] = __halves2bfloat162(h0, h1);
                    *(__nv_bfloat162*)&dl[(size_t)m * HEADD + nn] = __halves2bfloat162(l0, l1);
                }
            }
        }
    } else {
#pragma unroll
        for (int mf = 0; mf < 4; mf++) {
#pragma unroll
            for (int half = 0; half < 2; half++) {
                const int m = m0 + wm + mf * 16 + g + half * 8;
#pragma unroll
                for (int nf = 0; nf < 4; nf++) {
                    const int ncol = wn + nf * 8 + 2 * tg;
                    const int nn = nbase + ncol - 512;
                    float e = acc[mf][nf][half * 2]     * (1.0f / 16.0f);
                    float o = acc[mf][nf][half * 2 + 1] * (1.0f / 16.0f);
                    *(__half2*)&g_Vh[(size_t)m * VDIM + nn] =
                        __halves2half2(__float2half_rn(e), __float2half_rn(o));
                }
            }
        }
    }
}

// ===========================================================================
// Retention: 512 threads / 16 warps. per CTA (vh, qt, b): 64 q x 256 v.
// Q/K pre-scaled bf16 hi/lo planes from global via cp.async — no per-kt prep.
// 2 syncs/kt. K single-buffered, V double-buffered.
// ===========================================================================
#define QP 264
#define PS 72
#define PVV 264
#define OFF_QH 0
#define OFF_QL (64 * QP)
#define OFF_KH (2 * 64 * QP)
#define OFF_KL (3 * 64 * QP)
#define OFF_SH (4 * 64 * QP)
#define OFF_SL (OFF_SH + 64 * PS)
#define OFF_VB (OFF_SH + 2 * 64 * PS)
#define VPL(buf) (OFF_VB + (buf) * 64 * PVV)
#define RET_SMEM ((OFF_VB + 2 * 64 * PVV) * 2)

__global__ void __launch_bounds__(512, 1) retention_kernel(float* __restrict__ Out)
{
    extern __shared__ __align__(16) __half sm[];
    const uint32_t sb = smem_u32(sm);

    const int tid = threadIdx.x, wid = tid >> 5, lane = tid & 31;
    const int g = lane >> 2, tg = lane & 3;
    const int vh = blockIdx.x;
    const int qt = (int)gridDim.y - 1 - (int)blockIdx.y;   // heavy CTAs first
    const int b = blockIdx.z;
    const int q0 = qt * 64, base = b * SEQ;

    const int wm = (wid >> 2) * 16;
    const int wn = (wid & 3) * 16;
    const int wv = (wid & 3) * 64;

    const int arow_f = lane & 15;
    const int acol_f = (lane >> 4) << 3;
    const int krow_f = lane & 7;
    const int kcol_f = ((lane >> 3) & 1) * 8;
    const int b4row_f = lane & 15;
    const int b4col_f = (lane >> 4) << 3;

    const int kt_lo = (qt >= WINDOW - 1) ? qt - (WINDOW - 1) : 0;

    // ---- async plane loaders ----
    auto issue_qk = [&](uint32_t dstH, uint32_t dstL,
                        const __nv_bfloat16* srcH, const __nv_bfloat16* srcL, int r0) {
#pragma unroll
        for (int i = 0; i < 4; i++) {
            const int j = tid + i * 512;
            const int row = j >> 5, col8 = (j & 31) * 8;
            cp_async16(dstH + (uint32_t)(row * QP + col8) * 2,
                       srcH + (size_t)(base + r0 + row) * HEADD + col8);
            cp_async16(dstL + (uint32_t)(row * QP + col8) * 2,
                       srcL + (size_t)(base + r0 + row) * HEADD + col8);
        }
        CP_COMMIT();
    };
    auto issue_v = [&](int buf, int k0) {
        const int colbase = vh * 256;
#pragma unroll
        for (int i = 0; i < 4; i++) {
            const int j = tid + i * 512;
            const int row = j >> 5, col8 = (j & 31) * 8;
            cp_async16(sb + (uint32_t)(VPL(buf) + row * PVV + col8) * 2,
                       g_Vh + (size_t)(base + k0 + row) * VDIM + colbase + col8);
        }
        CP_COMMIT();
    };

    // prologue: Q planes + first K planes + first V tile
    issue_qk(sb + (uint32_t)OFF_QH * 2, sb + (uint32_t)OFF_QL * 2, g_Qh, g_Ql, q0);
    issue_qk(sb + (uint32_t)OFF_KH * 2, sb + (uint32_t)OFF_KL * 2, g_Kh, g_Kl, kt_lo * 64);
    issue_v(0, kt_lo * 64);

    float o[8][4];
#pragma unroll
    for (int n = 0; n < 8; n++)
#pragma unroll
        for (int c = 0; c < 4; c++) o[n][c] = 0.0f;

    int vbuf = 0;

    for (int kt = kt_lo; kt <= qt; kt++) {
        const int k0 = kt * 64;
        const bool full3 = (kt >= qt - 1);

        CP_WAIT(0);
        __syncthreads();                       // sync 1: K(kt), V(kt) (and Q) ready

        // ---- QK (bf16): warp tile 16q x 16k ----
        float s4[2][4];
#pragma unroll
        for (int n = 0; n < 2; n++)
#pragma unroll
            for (int c = 0; c < 4; c++) s4[n][c] = 0.0f;

#pragma unroll 4
        for (int ks = 0; ks < 16; ks++) {
            const int kk = ks * 16;
            uint32_t ah[4], al[4], bh[2][2], bl[2][2];
            const uint32_t offa = (uint32_t)((wm + arow_f) * QP + kk + acol_f) * 2;
            ldm_x4(ah, sb + (uint32_t)OFF_QH * 2 + offa);
            ldm_x4(al, sb + (uint32_t)OFF_QL * 2 + offa);
#pragma unroll
            for (int nf = 0; nf < 2; nf++) {
                const uint32_t off = (uint32_t)((wn + nf * 8 + krow_f) * QP + kk + kcol_f) * 2;
                ldm_x2(bh[nf], sb + (uint32_t)OFF_KH * 2 + off);
                ldm_x2(bl[nf], sb + (uint32_t)OFF_KL * 2 + off);
            }
            if (full3) {
#pragma unroll
                for (int nf = 0; nf < 2; nf++) {
                    mma16b(s4[nf], ah, bh[nf]);
                    mma16b(s4[nf], ah, bl[nf]);
                    mma16b(s4[nf], al, bh[nf]);
                }
            } else {
#pragma unroll
                for (int nf = 0; nf < 2; nf++) {
                    mma16b(s4[nf], ah, bh[nf]);
                    mma16b(s4[nf], ah, bl[nf]);
                }
            }
        }

        // ---- decay + store S ----
        if (kt < qt) {
            const int q_l = wm + g;
            const int dq0 = (q0 - k0) + q_l - (wn + 2 * tg);
            const float d00 = exp2f((float)dq0 * LOG2_GAMMA);
#pragma unroll
            for (int nf = 0; nf < 2; nf++) {
                const int k_l = wn + nf * 8 + 2 * tg;
                const float dc0 = (nf == 0) ? d00 : d00 * GAMMA_M8;
                const float dc1 = dc0 * GAMMA_INV;
                const float dc2 = dc0 * GAMMA_P8;
                const float dc3 = dc2 * GAMMA_INV;
                if (full3) {
                    __half h0, l0h, h1, l1h;
                    hsplit(s4[nf][0] * dc0, h0, l0h);
                    hsplit(s4[nf][1] * dc1, h1, l1h);
                    *(__half2*)(sm + OFF_SH + q_l * PS + k_l) = __halves2half2(h0, h1);
                    *(__half2*)(sm + OFF_SL + q_l * PS + k_l) = __halves2half2(l0h, l1h);
                    hsplit(s4[nf][2] * dc2, h0, l0h);
                    hsplit(s4[nf][3] * dc3, h1, l1h);
                    *(__half2*)(sm + OFF_SH + (q_l + 8) * PS + k_l) = __halves2half2(h0, h1);
                    *(__half2*)(sm + OFF_SL + (q_l + 8) * PS + k_l) = __halves2half2(l0h, l1h);
                } else {
                    *(__half2*)(sm + OFF_SH + q_l * PS + k_l) =
                        __halves2half2(__float2half_rn(s4[nf][0] * dc0),
                                       __float2half_rn(s4[nf][1] * dc1));
                    *(__half2*)(sm + OFF_SH + (q_l + 8) * PS + k_l) =
                        __halves2half2(__float2half_rn(s4[nf][2] * dc2),
                                       __float2half_rn(s4[nf][3] * dc3));
                }
            }
        } else {
            const int q_l = wm + g;
#pragma unroll
            for (int nf = 0; nf < 2; nf++) {
                const int k_l = wn + nf * 8 + 2 * tg;
#pragma unroll
                for (int c = 0; c < 4; c += 2) {
                    const int qq = q_l + (c >> 1) * 8;
                    __half h0, l0h, h1, l1h;
                    const int d0 = qq - k_l;
                    const float dec0 = (d0 >= 0) ? exp2f((float)d0 * LOG2_GAMMA) : 0.0f;
                    const float dec1 = (d0 - 1 >= 0) ? dec0 * GAMMA_INV : 0.0f;
                    hsplit(s4[nf][c] * dec0, h0, l0h);
                    hsplit(s4[nf][c + 1] * dec1, h1, l1h);
                    *(__half2*)(sm + OFF_SH + qq * PS + k_l) = __halves2half2(h0, h1);
                    *(__half2*)(sm + OFF_SL + qq * PS + k_l) = __halves2half2(l0h, l1h);
                }
            }
        }
        __syncthreads();                       // sync 2: S visible; K buffer free

        // prefetch next K + V (overlaps PV)
        if (kt < qt) {
            issue_qk(sb + (uint32_t)OFF_KH * 2, sb + (uint32_t)OFF_KL * 2, g_Kh, g_Kl, k0 + 64);
            issue_v(vbuf ^ 1, k0 + 64);
        }

        // ---- PV: warp tile 16q x 64v ----
        if (full3) {
#pragma unroll
            for (int ks = 0; ks < 4; ks++) {
                const int kk = ks * 16;
                uint32_t ah[4], al[4], bh[8][2];
                const uint32_t offa = (uint32_t)((wm + arow_f) * PS + kk + acol_f) * 2;
                ldm_x4(ah, sb + (uint32_t)OFF_SH * 2 + offa);
                ldm_x4(al, sb + (uint32_t)OFF_SL * 2 + offa);
#pragma unroll
                for (int p = 0; p < 4; p++) {
                    const uint32_t off = (uint32_t)((kk + b4row_f) * PVV + wv + p * 16 + b4col_f) * 2;
                    ldm_x4t(&bh[p * 2][0], sb + (uint32_t)VPL(vbuf) * 2 + off);
                }
#pragma unroll
                for (int nf = 0; nf < 8; nf++) {
                    mma16(o[nf], ah, bh[nf]);
                    mma16(o[nf], al, bh[nf]);
                }
            }
        } else {
#pragma unroll
            for (int ks = 0; ks < 4; ks++) {
                const int kk = ks * 16;
                uint32_t ah[4], bh[8][2];
                const uint32_t offa = (uint32_t)((wm + arow_f) * PS + kk + acol_f) * 2;
                ldm_x4(ah, sb + (uint32_t)OFF_SH * 2 + offa);
#pragma unroll
                for (int p = 0; p < 4; p++) {
                    const uint32_t off = (uint32_t)((kk + b4row_f) * PVV + wv + p * 16 + b4col_f) * 2;
                    ldm_x4t(&bh[p * 2][0], sb + (uint32_t)VPL(vbuf) * 2 + off);
                }
#pragma unroll
                for (int nf = 0; nf < 8; nf++)
                    mma16(o[nf], ah, bh[nf]);
            }
        }
        vbuf ^= 1;
    }

    // ---- store O ----
    const float inv = 1.0f / 262144.0f;
    const int q_l = wm + g;
#pragma unroll
    for (int nf = 0; nf < 8; nf++) {
        const int v = vh * 256 + wv + nf * 8 + 2 * tg;
        const size_t r0 = (size_t)(base + q0 + q_l) * VDIM + v;
        *(float2*)&Out[r0]            = make_float2(o[nf][0] * inv, o[nf][1] * inv);
        *(float2*)&Out[r0 + 8 * VDIM] = make_float2(o[nf][2] * inv, o[nf][3] * inv);
    }
}

// ===========================================================================
extern "C" void kernel_launch(void* const* d_in, const int* in_sizes, int n_in,
                              void* d_out, int out_size)
{
    const float* X  = (const float*)d_in[0];
    const float* WQ = (const float*)d_in[1];
    const float* WK = (const float*)d_in[2];
    const float* WV = (const float*)d_in[3];
    float* out = (float*)d_out;

    cudaFuncSetAttribute(proj_kernel, cudaFuncAttributeMaxDynamicSharedMemorySize, PROJ_SMEM);
    cudaFuncSetAttribute(retention_kernel, cudaFuncAttributeMaxDynamicSharedMemorySize, RET_SMEM);

    convert_x_kernel<<<(size_t)MROWS * HID / (256 * 8), 256>>>(X);
    convert_w_kernel<<<HID * 1024 / 256, 256>>>(WQ, WK, WV);
    proj_kernel<<<dim3(8, MROWS / 128), 256, PROJ_SMEM>>>();
    retention_kernel<<<dim3(2, SEQ / 64, BATCH), 512, RET_SMEM>>>(out);
}

// round 17
// speedup vs baseline: 1.1037x; 1.1037x over previous
#include <cuda_runtime.h>
#include <cuda_fp16.h>
#include <math.h>
#include <stdint.h>

#define BATCH   4
#define SEQ     4096
#define HID     2048
#define HEADD   256
#define VDIM    512
#define MROWS   (BATCH*SEQ)

#define LOG2_GAMMA (-0.045803686185410744f)
#define GAMMA_INV  (1.0322580645161290f)
#define GAMMA_P8   (0.7756998776f)
#define GAMMA_M8   (1.2891590567f)
#define WINDOW     7
#define L2_1E4_128 (0.10380962796523007f)

// Scratch (__device__ globals: allocation-free rule)
__device__ __half g_Xh[(size_t)MROWS * HID];    // X fp16-rounded
__device__ __half g_Wh[(size_t)HID * 1024];     // [WQ|WK|WV] * 1024, fp16
__device__ float  g_Q [(size_t)MROWS * HEADD];  // Qrot * sv^{+q/512}
__device__ float  g_K [(size_t)MROWS * HEADD];  // Krot * sv^{-k/512}
__device__ __half g_Vh[(size_t)MROWS * VDIM];   // V*64 fp16

// ---------------------------------------------------------------------------
__device__ __forceinline__ uint32_t smem_u32(const void* p) {
    uint32_t a;
    asm("{ .reg .u64 t; cvta.to.shared.u64 t, %1; cvt.u32.u64 %0, t; }" : "=r"(a) : "l"(p));
    return a;
}
__device__ __forceinline__ void cp_async16(uint32_t s, const void* g) {
    asm volatile("cp.async.cg.shared.global [%0], [%1], 16;" :: "r"(s), "l"(g) : "memory");
}
#define CP_COMMIT()  asm volatile("cp.async.commit_group;" ::: "memory")
#define CP_WAIT(N)   asm volatile("cp.async.wait_group %0;" :: "n"(N) : "memory")

__device__ __forceinline__ void ldm_x4(uint32_t* r, uint32_t a) {
    asm volatile("ldmatrix.sync.aligned.m8n8.x4.shared.b16 {%0,%1,%2,%3}, [%4];"
                 : "=r"(r[0]), "=r"(r[1]), "=r"(r[2]), "=r"(r[3]) : "r"(a));
}
__device__ __forceinline__ void ldm_x4t(uint32_t* r, uint32_t a) {
    asm volatile("ldmatrix.sync.aligned.m8n8.x4.trans.shared.b16 {%0,%1,%2,%3}, [%4];"
                 : "=r"(r[0]), "=r"(r[1]), "=r"(r[2]), "=r"(r[3]) : "r"(a));
}
__device__ __forceinline__ void ldm_x2(uint32_t* r, uint32_t a) {
    asm volatile("ldmatrix.sync.aligned.m8n8.x2.shared.b16 {%0,%1}, [%2];"
                 : "=r"(r[0]), "=r"(r[1]) : "r"(a));
}
__device__ __forceinline__ void mma16(float* d, const uint32_t* a, const uint32_t* b) {
    asm volatile("mma.sync.aligned.m16n8k16.row.col.f32.f16.f16.f32 "
                 "{%0,%1,%2,%3},{%4,%5,%6,%7},{%8,%9},{%0,%1,%2,%3};"
                 : "+f"(d[0]), "+f"(d[1]), "+f"(d[2]), "+f"(d[3])
                 : "r"(a[0]), "r"(a[1]), "r"(a[2]), "r"(a[3]), "r"(b[0]), "r"(b[1]));
}
__device__ __forceinline__ void mma3(float* d, const uint32_t* ah, const uint32_t* al,
                                     const uint32_t* bh, const uint32_t* bl) {
    mma16(d, ah, bh);
    mma16(d, ah, bl);
    mma16(d, al, bh);
}
__device__ __forceinline__ void hsplit(float x, __half& hi, __half& lo) {
    hi = __float2half_rn(x);
    lo = __float2half_rn(x - __half2float(hi));
}

// ===========================================================================
// Pre-convert kernels (R15)
// ===========================================================================
__global__ void __launch_bounds__(256) convert_x_kernel(const float* __restrict__ X)
{
    const size_t base = ((size_t)blockIdx.x * 256 + threadIdx.x) * 8;
    float4 a = *(const float4*)(X + base);
    float4 b = *(const float4*)(X + base + 4);
    __half2 ph[4];
    ph[0] = __halves2half2(__float2half_rn(a.x), __float2half_rn(a.y));
    ph[1] = __halves2half2(__float2half_rn(a.z), __float2half_rn(a.w));
    ph[2] = __halves2half2(__float2half_rn(b.x), __float2half_rn(b.y));
    ph[3] = __halves2half2(__float2half_rn(b.z), __float2half_rn(b.w));
    *(uint4*)(g_Xh + base) = *(uint4*)ph;
}

__global__ void __launch_bounds__(256) convert_w_kernel(const float* __restrict__ WQ,
                                                        const float* __restrict__ WK,
                                                        const float* __restrict__ WV)
{
    const int idx = blockIdx.x * 256 + threadIdx.x;
    const int k = idx >> 10, n = idx & 1023;
    float v;
    if (n < 256)      v = WQ[k * 256 + n];
    else if (n < 512) v = WK[k * 256 + (n - 256)];
    else              v = WV[k * 512 + (n - 512)];
    g_Wh[idx] = __float2half_rn(v * 1024.0f);
}

// ===========================================================================
// Projection: CTA 128x128, BK=64, 3 stages (32 iterations), 2 CTA/SM.
// ===========================================================================
#define PA 72
#define PB 136
#define APL(s)    ((s) * 128 * PA)
#define BPL(s)    (3 * 128 * PA + (s) * 64 * PB)
#define PROJ_SMEM ((3 * 128 * PA + 3 * 64 * PB) * 2)

__device__ __forceinline__ void proj_issue(uint32_t sb, int s, int chunk,
                                           int m0, int nbase, int tid)
{
    const int k0 = chunk * 64;
    // A: 128 rows x 64 halfs (128B) = 1024 x 16B
#pragma unroll
    for (int i = 0; i < 4; i++) {
        const int idx = tid + i * 256;
        const int row = idx >> 3;
        const int j = idx & 7;
        cp_async16(sb + (uint32_t)(APL(s) + row * PA + j * 8) * 2,
                   g_Xh + (size_t)(m0 + row) * HID + k0 + j * 8);
    }
    // B: 64 rows x 128 halfs (256B) = 1024 x 16B
#pragma unroll
    for (int i = 0; i < 4; i++) {
        const int idx = tid + i * 256;
        const int row = idx >> 4;
        const int j = idx & 15;
        cp_async16(sb + (uint32_t)(BPL(s) + row * PB + j * 8) * 2,
                   g_Wh + (size_t)(k0 + row) * 1024 + nbase + j * 8);
    }
    CP_COMMIT();
}

__global__ void __launch_bounds__(256, 2) proj_kernel()
{
    extern __shared__ __align__(16) __half sm[];
    const uint32_t sb = smem_u32(sm);

    const int tid = threadIdx.x, wid = tid >> 5, lane = tid & 31;
    const int g = lane >> 2, tg = lane & 3;
    const int m0 = blockIdx.y * 128;
    const int job = blockIdx.x;
    const int nbase = job * 128;

    const int wm = (wid >> 2) * 64, wn = (wid & 3) * 32;
    const int arow_f = lane & 15;
    const int acol_f = (lane >> 4) << 3;
    const int b4row_f = lane & 15;
    const int b4col_f = (lane >> 4) << 3;

    float acc[4][4][4];
#pragma unroll
    for (int a = 0; a < 4; a++)
#pragma unroll
        for (int b = 0; b < 4; b++)
#pragma unroll
            for (int c = 0; c < 4; c++) acc[a][b][c] = 0.0f;

    proj_issue(sb, 0, 0, m0, nbase, tid);
    proj_issue(sb, 1, 1, m0, nbase, tid);

    for (int kb = 0; kb < 32; kb++) {
        const int s = kb % 3;
        if (kb < 31) { CP_WAIT(1); } else { CP_WAIT(0); }
        __syncthreads();
        if (kb + 2 < 32) proj_issue(sb, (kb + 2) % 3, kb + 2, m0, nbase, tid);

#pragma unroll
        for (int k2 = 0; k2 < 4; k2++) {
            const int kk = k2 * 16;
            uint32_t ah[4][4], bh[4][2];
#pragma unroll
            for (int mf = 0; mf < 4; mf++) {
                const uint32_t off = (uint32_t)((wm + mf * 16 + arow_f) * PA + kk + acol_f) * 2;
                ldm_x4(ah[mf], sb + (uint32_t)APL(s) * 2 + off);
            }
#pragma unroll
            for (int p = 0; p < 2; p++) {
                const uint32_t off = (uint32_t)((kk + b4row_f) * PB + wn + p * 16 + b4col_f) * 2;
                ldm_x4t(&bh[p * 2][0], sb + (uint32_t)BPL(s) * 2 + off);
            }
#pragma unroll
            for (int mf = 0; mf < 4; mf++)
#pragma unroll
                for (int nf = 0; nf < 4; nf++)
                    mma16(acc[mf][nf], ah[mf], bh[nf]);
        }
    }

    // ---- epilogue (R15): per-nf constants hoisted ----
    const int mode = (job < 2) ? 1 : (job < 4) ? 2 : 0;

    if (mode != 0) {
        float invf_v[4], lgsv_v[4];
#pragma unroll
        for (int nf = 0; nf < 4; nf++) {
            const int nn = (nbase + wn + nf * 8 + 2 * tg) & 255;
            invf_v[nf] = exp2f((float)(nn >> 1) * (-L2_1E4_128));
            lgsv_v[nf] = __log2f(((float)nn + 102.4f) * (1.0f / 358.4f));
        }
        float* dst = (mode == 1) ? g_Q : g_K;
        const float sgn = (mode == 1) ? (1.0f / 512.0f) : (-1.0f / 512.0f);
#pragma unroll
        for (int mf = 0; mf < 4; mf++) {
#pragma unroll
            for (int half = 0; half < 2; half++) {
                const int m = m0 + wm + mf * 16 + g + half * 8;
                const float spos = (float)(m & (SEQ - 1));
                const float e512 = spos * sgn;
#pragma unroll
                for (int nf = 0; nf < 4; nf++) {
                    const int nn = (nbase + wn + nf * 8 + 2 * tg) & 255;
                    float e = acc[mf][nf][half * 2]     * (1.0f / 1024.0f);
                    float o = acc[mf][nf][half * 2 + 1] * (1.0f / 1024.0f);
                    float sn, cs;
                    sincosf(spos * invf_v[nf], &sn, &cs);
                    const float sc = exp2f(lgsv_v[nf] * e512);
                    const float ne = (e * cs - o * sn) * sc;
                    const float no = (o * cs + e * sn) * sc;
                    *(float2*)&dst[(size_t)m * HEADD + nn] = make_float2(ne, no);
                }
            }
        }
    } else {
#pragma unroll
        for (int mf = 0; mf < 4; mf++) {
#pragma unroll
            for (int half = 0; half < 2; half++) {
                const int m = m0 + wm + mf * 16 + g + half * 8;
#pragma unroll
                for (int nf = 0; nf < 4; nf++) {
                    const int ncol = wn + nf * 8 + 2 * tg;
                    const int nn = nbase + ncol - 512;
                    float e = acc[mf][nf][half * 2]     * (1.0f / 16.0f);
                    float o = acc[mf][nf][half * 2 + 1] * (1.0f / 16.0f);
                    *(__half2*)&g_Vh[(size_t)m * VDIM + nn] =
                        __halves2half2(__float2half_rn(e), __float2half_rn(o));
                }
            }
        }
    }
}

// ===========================================================================
// Retention (R15 champion, byte-identical): 512 threads, WINDOW=7.
// ===========================================================================
#define QP 264
#define PS 72
#define PVV 264
#define OFF_QH 0
#define OFF_QL (64 * QP)
#define OFF_KH (2 * 64 * QP)
#define OFF_KL (3 * 64 * QP)
#define OFF_SH (4 * 64 * QP)
#define OFF_SL (OFF_SH + 64 * PS)
#define OFF_VB (OFF_SH + 2 * 64 * PS)
#define VPL(buf) (OFF_VB + (buf) * 64 * PVV)
#define RET_SMEM ((OFF_VB + 2 * 64 * PVV) * 2)

__global__ void __launch_bounds__(512, 1) retention_kernel(float* __restrict__ Out)
{
    extern __shared__ __align__(16) __half sm[];
    const uint32_t sb = smem_u32(sm);

    const int tid = threadIdx.x, wid = tid >> 5, lane = tid & 31;
    const int g = lane >> 2, tg = lane & 3;
    const int vh = blockIdx.x;
    const int qt = (int)gridDim.y - 1 - (int)blockIdx.y;
    const int b = blockIdx.z;
    const int q0 = qt * 64, base = b * SEQ;

    const int wm = (wid >> 2) * 16;
    const int wn = (wid & 3) * 16;
    const int wv = (wid & 3) * 64;

    const int arow_f = lane & 15;
    const int acol_f = (lane >> 4) << 3;
    const int krow_f = lane & 7;
    const int kcol_f = ((lane >> 3) & 1) * 8;
    const int b4row_f = lane & 15;
    const int b4col_f = (lane >> 4) << 3;

    const int kt_lo = (qt >= WINDOW - 1) ? qt - (WINDOW - 1) : 0;

    const int c4 = (tid & 63) * 4;
    const float lg0 = __log2f(((float)c4 + 102.4f) * (1.0f / 358.4f));
    const float lg1 = __log2f(((float)c4 + 104.4f) * (1.0f / 358.4f));
    const float eq = (float)q0 * (1.0f / 512.0f);
    const float fq0 = exp2f(-lg0 * eq + 6.0f), fq1 = exp2f(-lg1 * eq + 6.0f);
    const float fk0 = exp2f( lg0 * eq + 6.0f), fk1 = exp2f( lg1 * eq + 6.0f);

    auto issue_v = [&](int buf, int k0) {
        const int colbase = vh * 256;
#pragma unroll
        for (int i = 0; i < 4; i++) {
            const int j = tid + i * 512;
            const int row = j >> 5, col8 = (j & 31) * 8;
            cp_async16(sb + (uint32_t)(VPL(buf) + row * PVV + col8) * 2,
                       g_Vh + (size_t)(base + k0 + row) * VDIM + colbase + col8);
        }
        CP_COMMIT();
    };

    issue_v(0, kt_lo * 64);

#pragma unroll 4
    for (int i = 0; i < 8; i++) {
        const int idx = tid + i * 512;
        const int row = idx >> 6;
        float4 v = *(const float4*)(g_Q + (size_t)(base + q0 + row) * HEADD + c4);
        __half h0, l0h, h1, l1h, h2, l2h, h3, l3h;
        hsplit(v.x * fq0, h0, l0h); hsplit(v.y * fq0, h1, l1h);
        hsplit(v.z * fq1, h2, l2h); hsplit(v.w * fq1, h3, l3h);
        __half* ph = sm + OFF_QH + row * QP + c4;
        __half* pl = sm + OFF_QL + row * QP + c4;
        *(__half2*)(ph) = __halves2half2(h0, h1);  *(__half2*)(ph + 2) = __halves2half2(h2, h3);
        *(__half2*)(pl) = __halves2half2(l0h, l1h); *(__half2*)(pl + 2) = __halves2half2(l2h, l3h);
    }

    float o[8][4];
#pragma unroll
    for (int n = 0; n < 8; n++)
#pragma unroll
        for (int c = 0; c < 4; c++) o[n][c] = 0.0f;

    int vbuf = 0;

    for (int kt = kt_lo; kt <= qt; kt++) {
        const int k0 = kt * 64;
        const bool full3 = (kt >= qt - 1);

#pragma unroll 4
        for (int i = 0; i < 8; i++) {
            const int idx = tid + i * 512;
            const int row = idx >> 6;
            float4 v = *(const float4*)(g_K + (size_t)(base + k0 + row) * HEADD + c4);
            __half h0, l0h, h1, l1h, h2, l2h, h3, l3h;
            hsplit(v.x * fk0, h0, l0h); hsplit(v.y * fk0, h1, l1h);
            hsplit(v.z * fk1, h2, l2h); hsplit(v.w * fk1, h3, l3h);
            __half* ph = sm + OFF_KH + row * QP + c4;
            *(__half2*)(ph) = __halves2half2(h0, h1);  *(__half2*)(ph + 2) = __halves2half2(h2, h3);
            if (full3) {
                __half* pl = sm + OFF_KL + row * QP + c4;
                *(__half2*)(pl) = __halves2half2(l0h, l1h); *(__half2*)(pl + 2) = __halves2half2(l2h, l3h);
            }
        }
        __syncthreads();                       // sync 1

        if (kt < qt) issue_v(vbuf ^ 1, k0 + 64);

        float s4[2][4];
#pragma unroll
        for (int n = 0; n < 2; n++)
#pragma unroll
            for (int c = 0; c < 4; c++) s4[n][c] = 0.0f;

        if (full3) {
#pragma unroll 4
            for (int ks = 0; ks < 16; ks++) {
                const int kk = ks * 16;
                uint32_t ah[4], al[4], bh[2][2], bl[2][2];
                const uint32_t offa = (uint32_t)((wm + arow_f) * QP + kk + acol_f) * 2;
                ldm_x4(ah, sb + (uint32_t)OFF_QH * 2 + offa);
                ldm_x4(al, sb + (uint32_t)OFF_QL * 2 + offa);
#pragma unroll
                for (int nf = 0; nf < 2; nf++) {
                    const uint32_t off = (uint32_t)((wn + nf * 8 + krow_f) * QP + kk + kcol_f) * 2;
                    ldm_x2(bh[nf], sb + (uint32_t)OFF_KH * 2 + off);
                    ldm_x2(bl[nf], sb + (uint32_t)OFF_KL * 2 + off);
                }
#pragma unroll
                for (int nf = 0; nf < 2; nf++)
                    mma3(s4[nf], ah, al, bh[nf], bl[nf]);
            }
        } else {
#pragma unroll 4
            for (int ks = 0; ks < 16; ks++) {
                const int kk = ks * 16;
                uint32_t ah[4], bh[2][2];
                const uint32_t offa = (uint32_t)((wm + arow_f) * QP + kk + acol_f) * 2;
                ldm_x4(ah, sb + (uint32_t)OFF_QH * 2 + offa);
#pragma unroll
                for (int nf = 0; nf < 2; nf++) {
                    const uint32_t off = (uint32_t)((wn + nf * 8 + krow_f) * QP + kk + kcol_f) * 2;
                    ldm_x2(bh[nf], sb + (uint32_t)OFF_KH * 2 + off);
                }
#pragma unroll
                for (int nf = 0; nf < 2; nf++)
                    mma16(s4[nf], ah, bh[nf]);
            }
        }

        if (kt < qt) {
            const int q_l = wm + g;
            const int dq0 = (q0 - k0) + q_l - (wn + 2 * tg);
            const float d00 = exp2f((float)dq0 * LOG2_GAMMA);
#pragma unroll
            for (int nf = 0; nf < 2; nf++) {
                const int k_l = wn + nf * 8 + 2 * tg;
                const float dc0 = (nf == 0) ? d00 : d00 * GAMMA_M8;
                const float dc1 = dc0 * GAMMA_INV;
                const float dc2 = dc0 * GAMMA_P8;
                const float dc3 = dc2 * GAMMA_INV;
                if (full3) {
                    __half h0, l0h, h1, l1h;
                    hsplit(s4[nf][0] * dc0, h0, l0h);
                    hsplit(s4[nf][1] * dc1, h1, l1h);
                    *(__half2*)(sm + OFF_SH + q_l * PS + k_l) = __halves2half2(h0, h1);
                    *(__half2*)(sm + OFF_SL + q_l * PS + k_l) = __halves2half2(l0h, l1h);
                    hsplit(s4[nf][2] * dc2, h0, l0h);
                    hsplit(s4[nf][3] * dc3, h1, l1h);
                    *(__half2*)(sm + OFF_SH + (q_l + 8) * PS + k_l) = __halves2half2(h0, h1);
                    *(__half2*)(sm + OFF_SL + (q_l + 8) * PS + k_l) = __halves2half2(l0h, l1h);
                } else {
                    *(__half2*)(sm + OFF_SH + q_l * PS + k_l) =
                        __halves2half2(__float2half_rn(s4[nf][0] * dc0),
                                       __float2half_rn(s4[nf][1] * dc1));
                    *(__half2*)(sm + OFF_SH + (q_l + 8) * PS + k_l) =
                        __halves2half2(__float2half_rn(s4[nf][2] * dc2),
                                       __float2half_rn(s4[nf][3] * dc3));
                }
            }
        } else {
            const int q_l = wm + g;
#pragma unroll
            for (int nf = 0; nf < 2; nf++) {
                const int k_l = wn + nf * 8 + 2 * tg;
#pragma unroll
                for (int c = 0; c < 4; c += 2) {
                    const int qq = q_l + (c >> 1) * 8;
                    __half h0, l0h, h1, l1h;
                    const int d0 = qq - k_l;
                    const float dec0 = (d0 >= 0) ? exp2f((float)d0 * LOG2_GAMMA) : 0.0f;
                    const float dec1 = (d0 - 1 >= 0) ? dec0 * GAMMA_INV : 0.0f;
                    hsplit(s4[nf][c] * dec0, h0, l0h);
                    hsplit(s4[nf][c + 1] * dec1, h1, l1h);
                    *(__half2*)(sm + OFF_SH + qq * PS + k_l) = __halves2half2(h0, h1);
                    *(__half2*)(sm + OFF_SL + qq * PS + k_l) = __halves2half2(l0h, l1h);
                }
            }
        }
        __syncthreads();                       // sync 2

        if (kt < qt) { CP_WAIT(1); } else { CP_WAIT(0); }
        __syncthreads();                       // sync 3

        if (full3) {
#pragma unroll
            for (int ks = 0; ks < 4; ks++) {
                const int kk = ks * 16;
                uint32_t ah[4], al[4], bh[8][2];
                const uint32_t offa = (uint32_t)((wm + arow_f) * PS + kk + acol_f) * 2;
                ldm_x4(ah, sb + (uint32_t)OFF_SH * 2 + offa);
                ldm_x4(al, sb + (uint32_t)OFF_SL * 2 + offa);
#pragma unroll
                for (int p = 0; p < 4; p++) {
                    const uint32_t off = (uint32_t)((kk + b4row_f) * PVV + wv + p * 16 + b4col_f) * 2;
                    ldm_x4t(&bh[p * 2][0], sb + (uint32_t)VPL(vbuf) * 2 + off);
                }
#pragma unroll
                for (int nf = 0; nf < 8; nf++) {
                    mma16(o[nf], ah, bh[nf]);
                    mma16(o[nf], al, bh[nf]);
                }
            }
        } else {
#pragma unroll
            for (int ks = 0; ks < 4; ks++) {
                const int kk = ks * 16;
                uint32_t ah[4], bh[8][2];
                const uint32_t offa = (uint32_t)((wm + arow_f) * PS + kk + acol_f) * 2;
                ldm_x4(ah, sb + (uint32_t)OFF_SH * 2 + offa);
#pragma unroll
                for (int p = 0; p < 4; p++) {
                    const uint32_t off = (uint32_t)((kk + b4row_f) * PVV + wv + p * 16 + b4col_f) * 2;
                    ldm_x4t(&bh[p * 2][0], sb + (uint32_t)VPL(vbuf) * 2 + off);
                }
#pragma unroll
                for (int nf = 0; nf < 8; nf++)
                    mma16(o[nf], ah, bh[nf]);
            }
        }
        vbuf ^= 1;
    }

    const float inv = 1.0f / 262144.0f;
    const int q_l = wm + g;
#pragma unroll
    for (int nf = 0; nf < 8; nf++) {
        const int v = vh * 256 + wv + nf * 8 + 2 * tg;
        const size_t r0 = (size_t)(base + q0 + q_l) * VDIM + v;
        *(float2*)&Out[r0]            = make_float2(o[nf][0] * inv, o[nf][1] * inv);
        *(float2*)&Out[r0 + 8 * VDIM] = make_float2(o[nf][2] * inv, o[nf][3] * inv);
    }
}

// ===========================================================================
extern "C" void kernel_launch(void* const* d_in, const int* in_sizes, int n_in,
                              void* d_out, int out_size)
{
    const float* X  = (const float*)d_in[0];
    const float* WQ = (const float*)d_in[1];
    const float* WK = (const float*)d_in[2];
    const float* WV = (const float*)d_in[3];
    float* out = (float*)d_out;

    cudaFuncSetAttribute(proj_kernel, cudaFuncAttributeMaxDynamicSharedMemorySize, PROJ_SMEM);
    cudaFuncSetAttribute(retention_kernel, cudaFuncAttributeMaxDynamicSharedMemorySize, RET_SMEM);

    convert_x_kernel<<<(size_t)MROWS * HID / (256 * 8), 256>>>(X);
    convert_w_kernel<<<HID * 1024 / 256, 256>>>(WQ, WK, WV);
    proj_kernel<<<dim3(8, MROWS / 128), 256, PROJ_SMEM>>>();
    retention_kernel<<<dim3(2, SEQ / 64, BATCH), 512, RET_SMEM>>>(out);
}